// round 4
// baseline (speedup 1.0000x reference)
#include <cuda_runtime.h>
#include <cuda_bf16.h>
#include <math.h>

// Problem constants (fixed by setup_inputs): B=2048, K=128, D=256
#define BB 2048
#define KK 128
#define DD 256

#define BT 32      // b-rows per block
#define KT 32      // k-cols per block
#define PITCH 260  // smem row pitch in floats -> conflict-free LDS.128
#define NTHREADS 256

typedef unsigned long long ull;

__device__ __forceinline__ void fma2(ull& d, ull a, ull b) {
    // packed fp32x2 FMA: d.lo += a.lo*b.lo ; d.hi += a.hi*b.hi
    asm("fma.rn.f32x2 %0, %1, %2, %3;" : "=l"(d) : "l"(a), "l"(b), "l"(d));
}
__device__ __forceinline__ float lo32(ull v) { return __uint_as_float((unsigned)v); }
__device__ __forceinline__ float hi32(ull v) { return __uint_as_float((unsigned)(v >> 32)); }
__device__ __forceinline__ float red4(ull a, ull b) {
    return (lo32(a) + hi32(a)) + (lo32(b) + hi32(b));
}

// logits[b][k] = 2*an_k * asinh( 2*(S*xa + T*ya)*den / (den^2 - (S^2*x2 + 2*S*T*xy + T^2*y2)) )
// g = z_k . y_b, xy = s_k*g, ya = t_k*g, S = 1+2xy+y2, den = 1+2xy+x2*y2, T = 1-x2

__global__ void __launch_bounds__(NTHREADS, 2)
mlr_logits_kernel(const float* __restrict__ Y,   // output_before (B, D)
                  const float* __restrict__ Z,   // z_mlr (K, D)
                  const float* __restrict__ R,   // mlr_r (K, 1)
                  float* __restrict__ Out)       // (B, K)
{
    extern __shared__ float smem[];
    float* ysm   = smem;                    // BT * PITCH
    float* zsm   = ysm + BT * PITCH;        // KT * PITCH
    float* part  = zsm + KT * PITCH;        // 256 partials (rows 0..31 y, 32..63 z)
    float* s_s   = part + NTHREADS;         // KT
    float* s_t   = s_s + KT;                // KT
    float* s_x2  = s_t + KT;                // KT
    float* s_xa  = s_x2 + KT;               // KT
    float* s_an2 = s_xa + KT;               // KT
    float* s_y2  = s_an2 + KT;              // BT

    const int tid = threadIdx.x;
    const int b0  = blockIdx.x * BT;
    const int k0  = blockIdx.y * KT;

    // ---- load Y tile (BT x D) and Z tile (KT x D), float4, coalesced ----
    {
        #pragma unroll
        for (int idx = tid; idx < BT * (DD / 4); idx += NTHREADS) {
            int row = idx >> 6;
            int c4  = idx & 63;
            float4 v = reinterpret_cast<const float4*>(Y + (size_t)(b0 + row) * DD)[c4];
            *reinterpret_cast<float4*>(&ysm[row * PITCH + c4 * 4]) = v;
        }
        #pragma unroll
        for (int idx = tid; idx < KT * (DD / 4); idx += NTHREADS) {
            int row = idx >> 6;
            int c4  = idx & 63;
            float4 v = reinterpret_cast<const float4*>(Z + (size_t)(k0 + row) * DD)[c4];
            *reinterpret_cast<float4*>(&zsm[row * PITCH + c4 * 4]) = v;
        }
    }
    __syncthreads();

    // ---- cooperative row-norm partials: 4 threads per row, 64-elem quarters ----
    {
        const int row = tid >> 2;          // 0..63 (0..31 -> y, 32..63 -> z)
        const int q   = tid & 3;
        const float* base = (row < 32) ? (ysm + row * PITCH) : (zsm + (row - 32) * PITCH);
        base += q * 64;
        float a0 = 0.f, a1 = 0.f, a2 = 0.f, a3 = 0.f;
        #pragma unroll
        for (int j = 0; j < 16; j++) {
            float4 v = *reinterpret_cast<const float4*>(base + j * 4);
            a0 = fmaf(v.x, v.x, a0);  a1 = fmaf(v.y, v.y, a1);
            a2 = fmaf(v.z, v.z, a2);  a3 = fmaf(v.w, v.w, a3);
        }
        part[tid] = (a0 + a1) + (a2 + a3);
    }
    __syncthreads();

    // ---- combine partials + per-k scalars ----
    if (tid < BT) {
        s_y2[tid] = (part[tid * 4 + 0] + part[tid * 4 + 1]) +
                    (part[tid * 4 + 2] + part[tid * 4 + 3]);
    } else if (tid < BT + KT) {
        int row = tid - BT;
        int p   = 128 + row * 4;
        float zn2 = (part[p + 0] + part[p + 1]) + (part[p + 2] + part[p + 3]);
        float zn  = sqrtf(zn2);
        float r   = R[k0 + row];
        float un  = fmaxf(fabsf(r) * zn, 1e-15f);
        float s   = -tanhf(un) * r / un;
        float th  = tanhf(r);
        float ic2 = 1.0f - th * th;      // 1/cosh(r)^2
        float an  = zn * ic2;
        float t   = ic2 / fmaxf(an, 1e-12f);
        s_s[row]   = s;
        s_t[row]   = t;
        s_x2[row]  = s * s * zn2;
        s_xa[row]  = s * zn2 * t;
        s_an2[row] = 2.0f * an;
    }
    __syncthreads();

    // ---- main GEMM: 16(ty) x 16(tx) threads, each 2(b) x 2(k), f32x2, pipelined ----
    const int ty = tid >> 4;   // 0..15 -> b rows ty*2, ty*2+1
    const int tx = tid & 15;   // 0..15 -> k cols tx, tx+16

    const float* yb  = ysm + (ty * 2) * PITCH;
    const float* z0p = zsm + tx * PITCH;
    const float* z1p = zsm + (tx + 16) * PITCH;

    ull a00A = 0, a00B = 0, a01A = 0, a01B = 0;
    ull a10A = 0, a10B = 0, a11A = 0, a11B = 0;

    // double-buffered register prefetch
    ulonglong2 y0c, y1c, z0c, z1c;   // current
    ulonglong2 y0n, y1n, z0n, z1n;   // next

    y0c = *reinterpret_cast<const ulonglong2*>(yb);
    y1c = *reinterpret_cast<const ulonglong2*>(yb + PITCH);
    z0c = *reinterpret_cast<const ulonglong2*>(z0p);
    z1c = *reinterpret_cast<const ulonglong2*>(z1p);

    #pragma unroll 4
    for (int d4 = 0; d4 < DD / 4 - 1; d4++) {
        const int off = (d4 + 1) * 4;
        // prefetch next iteration (independent of current FMAs)
        y0n = *reinterpret_cast<const ulonglong2*>(yb + off);
        y1n = *reinterpret_cast<const ulonglong2*>(yb + PITCH + off);
        z0n = *reinterpret_cast<const ulonglong2*>(z0p + off);
        z1n = *reinterpret_cast<const ulonglong2*>(z1p + off);
        // consume current
        fma2(a00A, y0c.x, z0c.x);  fma2(a00B, y0c.y, z0c.y);
        fma2(a01A, y0c.x, z1c.x);  fma2(a01B, y0c.y, z1c.y);
        fma2(a10A, y1c.x, z0c.x);  fma2(a10B, y1c.y, z0c.y);
        fma2(a11A, y1c.x, z1c.x);  fma2(a11B, y1c.y, z1c.y);
        y0c = y0n; y1c = y1n; z0c = z0n; z1c = z1n;
    }
    fma2(a00A, y0c.x, z0c.x);  fma2(a00B, y0c.y, z0c.y);
    fma2(a01A, y0c.x, z1c.x);  fma2(a01B, y0c.y, z1c.y);
    fma2(a10A, y1c.x, z0c.x);  fma2(a10B, y1c.y, z0c.y);
    fma2(a11A, y1c.x, z1c.x);  fma2(a11B, y1c.y, z1c.y);

    // ---- epilogue: 4 outputs per thread ----
    float gg[2][2];
    gg[0][0] = red4(a00A, a00B);
    gg[0][1] = red4(a01A, a01B);
    gg[1][0] = red4(a10A, a10B);
    gg[1][1] = red4(a11A, a11B);

    #pragma unroll
    for (int j = 0; j < 2; j++) {
        int kl = tx + 16 * j;
        float s   = s_s[kl];
        float t   = s_t[kl];
        float x2  = s_x2[kl];
        float xa  = s_xa[kl];
        float an2 = s_an2[kl];
        float T   = 1.0f - x2;
        #pragma unroll
        for (int i = 0; i < 2; i++) {
            int bl = ty * 2 + i;
            float g  = gg[i][j];
            float y2 = s_y2[bl];
            float xy = s * g;
            float ya = t * g;
            float S   = fmaf(2.0f, xy, 1.0f) + y2;
            float den = fmaf(2.0f, xy, 1.0f) + x2 * y2;
            float P   = S * S * x2 + 2.0f * S * T * xy + T * T * y2;
            float v   = 2.0f * (S * xa + T * ya) * den / (den * den - P);
            Out[(size_t)(b0 + bl) * KK + (k0 + kl)] = an2 * asinhf(v);
        }
    }
}

extern "C" void kernel_launch(void* const* d_in, const int* in_sizes, int n_in,
                              void* d_out, int out_size)
{
    const float* Y = (const float*)d_in[0];   // output_before (2048, 256)
    const float* Z = (const float*)d_in[1];   // z_mlr (128, 256)
    const float* R = (const float*)d_in[2];   // mlr_r (128, 1)
    float* Out = (float*)d_out;               // (2048, 128)

    size_t shmem = (size_t)(BT * PITCH + KT * PITCH + NTHREADS + 5 * KT + BT) * sizeof(float);
    cudaFuncSetAttribute(mlr_logits_kernel,
                         cudaFuncAttributeMaxDynamicSharedMemorySize, (int)shmem);

    dim3 grid(BB / BT, KK / KT);   // 64 x 4 = 256 blocks
    dim3 block(NTHREADS);
    mlr_logits_kernel<<<grid, block, shmem>>>(Y, Z, R, Out);
}

// round 5
// speedup vs baseline: 1.1382x; 1.1382x over previous
#include <cuda_runtime.h>
#include <cuda_bf16.h>
#include <math.h>
#include <stdint.h>

// Problem constants (fixed by setup_inputs): B=2048, K=128, D=256
#define BB 2048
#define KK 128
#define DD 256

#define BM 64      // b-rows per block
#define BN 16      // k-cols per block
#define PITCH 260  // smem row pitch in floats
#define NTHREADS 256

__device__ __forceinline__ uint32_t f2tf32(float v) {
    uint32_t r; asm("cvt.rna.tf32.f32 %0, %1;" : "=r"(r) : "f"(v)); return r;
}

__device__ __forceinline__ void mma_tf32(float* d, const uint32_t* a, uint32_t b0, uint32_t b1) {
    asm volatile("mma.sync.aligned.m16n8k8.row.col.f32.tf32.tf32.f32 "
                 "{%0,%1,%2,%3}, {%4,%5,%6,%7}, {%8,%9}, {%0,%1,%2,%3};"
                 : "+f"(d[0]), "+f"(d[1]), "+f"(d[2]), "+f"(d[3])
                 : "r"(a[0]), "r"(a[1]), "r"(a[2]), "r"(a[3]), "r"(b0), "r"(b1));
}

// logits[b][k] = 2*an_k * asinh( 2*(S*xa + T*ya)*den / (den^2 - (S^2*x2 + 2*S*T*xy + T^2*y2)) )
// g = z_k . y_b, xy = s_k*g, ya = t_k*g, S = 1+2xy+y2, den = 1+2xy+x2*y2, T = 1-x2

__global__ void __launch_bounds__(NTHREADS, 2)
mlr_logits_kernel(const float* __restrict__ Y,   // output_before (B, D)
                  const float* __restrict__ Z,   // z_mlr (K, D)
                  const float* __restrict__ R,   // mlr_r (K, 1)
                  float* __restrict__ Out)       // (B, K)
{
    extern __shared__ float smem[];
    float* ysm   = smem;                     // BM * PITCH (full fp32 Y tile)
    float* zbig  = ysm  + BM * PITCH;        // BN * PITCH (tf32-hi bit patterns)
    float* zres  = zbig + BN * PITCH;        // BN * PITCH (tf32-lo bit patterns)
    float* ypart = zres + BN * PITCH;        // 256
    float* zpart = ypart + NTHREADS;         // 64
    float* s_s   = zpart + 64;               // BN
    float* s_t   = s_s + BN;                 // BN
    float* s_x2  = s_t + BN;                 // BN
    float* s_xa  = s_x2 + BN;                // BN
    float* s_an2 = s_xa + BN;                // BN
    float* s_y2  = s_an2 + BN;               // BM

    const int tid  = threadIdx.x;
    const int b0   = blockIdx.x * BM;
    const int k0   = blockIdx.y * BN;
    const int warp = tid >> 5;
    const int lane = tid & 31;

    // ---- load Y tile (BM x D) full precision ----
    #pragma unroll
    for (int idx = tid; idx < BM * (DD / 4); idx += NTHREADS) {
        int row = idx >> 6;
        int c4  = idx & 63;
        float4 v = reinterpret_cast<const float4*>(Y + (size_t)(b0 + row) * DD)[c4];
        *reinterpret_cast<float4*>(&ysm[row * PITCH + c4 * 4]) = v;
    }

    // ---- load Z tile (BN x D) and split into tf32 hi/lo ----
    #pragma unroll
    for (int idx = tid; idx < BN * (DD / 4); idx += NTHREADS) {
        int row = idx >> 6;
        int c4  = idx & 63;
        float4 v = reinterpret_cast<const float4*>(Z + (size_t)(k0 + row) * DD)[c4];
        float4 hb, rb;
        {
            uint32_t h;
            h = f2tf32(v.x); hb.x = __uint_as_float(h); rb.x = __uint_as_float(f2tf32(v.x - __uint_as_float(h)));
            h = f2tf32(v.y); hb.y = __uint_as_float(h); rb.y = __uint_as_float(f2tf32(v.y - __uint_as_float(h)));
            h = f2tf32(v.z); hb.z = __uint_as_float(h); rb.z = __uint_as_float(f2tf32(v.z - __uint_as_float(h)));
            h = f2tf32(v.w); hb.w = __uint_as_float(h); rb.w = __uint_as_float(f2tf32(v.w - __uint_as_float(h)));
        }
        *reinterpret_cast<float4*>(&zbig[row * PITCH + c4 * 4]) = hb;
        *reinterpret_cast<float4*>(&zres[row * PITCH + c4 * 4]) = rb;
    }
    __syncthreads();

    // ---- cooperative row norms: y (64 rows x 4 thr), z (16 rows x 4 thr) ----
    {
        const int row = tid >> 2;   // 0..63
        const int q   = tid & 3;
        const float* yr = ysm + row * PITCH + q * 64;
        float a0 = 0.f, a1 = 0.f, a2 = 0.f, a3 = 0.f;
        #pragma unroll
        for (int j = 0; j < 16; j++) {
            float4 v = *reinterpret_cast<const float4*>(yr + j * 4);
            a0 = fmaf(v.x, v.x, a0);  a1 = fmaf(v.y, v.y, a1);
            a2 = fmaf(v.z, v.z, a2);  a3 = fmaf(v.w, v.w, a3);
        }
        ypart[tid] = (a0 + a1) + (a2 + a3);
    }
    if (tid < 64) {
        const int row = tid >> 2;   // 0..15
        const int q   = tid & 3;
        const float* zh = zbig + row * PITCH + q * 64;
        const float* zl = zres + row * PITCH + q * 64;
        float a0 = 0.f, a1 = 0.f, a2 = 0.f, a3 = 0.f;
        #pragma unroll
        for (int j = 0; j < 16; j++) {
            float4 h = *reinterpret_cast<const float4*>(zh + j * 4);
            float4 l = *reinterpret_cast<const float4*>(zl + j * 4);
            float vx = h.x + l.x, vy = h.y + l.y, vz = h.z + l.z, vw = h.w + l.w;
            a0 = fmaf(vx, vx, a0);  a1 = fmaf(vy, vy, a1);
            a2 = fmaf(vz, vz, a2);  a3 = fmaf(vw, vw, a3);
        }
        zpart[tid] = (a0 + a1) + (a2 + a3);
    }
    __syncthreads();

    if (tid < BN) {
        int row = tid;
        float zn2 = (zpart[row * 4 + 0] + zpart[row * 4 + 1]) +
                    (zpart[row * 4 + 2] + zpart[row * 4 + 3]);
        float zn  = sqrtf(zn2);
        float r   = R[k0 + row];
        float un  = fmaxf(fabsf(r) * zn, 1e-15f);
        float s   = -tanhf(un) * r / un;
        float th  = tanhf(r);
        float ic2 = 1.0f - th * th;      // 1/cosh(r)^2
        float an  = zn * ic2;
        float t   = ic2 / fmaxf(an, 1e-12f);
        s_s[row]   = s;
        s_t[row]   = t;
        s_x2[row]  = s * s * zn2;
        s_xa[row]  = s * zn2 * t;
        s_an2[row] = 2.0f * an;
    } else if (tid >= 32 && tid < 32 + BM) {
        int row = tid - 32;
        s_y2[row] = (ypart[row * 4 + 0] + ypart[row * 4 + 1]) +
                    (ypart[row * 4 + 2] + ypart[row * 4 + 3]);
    }
    __syncthreads();

    // ---- tensor-core GEMM: warp -> 16(m) x 8(n) tile, m16n8k8 tf32, 3xTF32 ----
    const int mw = (warp >> 1) * 16;    // warp m offset within block: 0,16,32,48
    const int nw = (warp & 1) * 8;      // warp n offset: 0,8
    const int g  = lane >> 2;           // group 0..7
    const int c  = lane & 3;            // thread-in-group

    const float* aP = ysm  + (mw + g) * PITCH + c;
    const float* bH = zbig + (nw + g) * PITCH + c;
    const float* bL = zres + (nw + g) * PITCH + c;

    float accP[4] = {0.f, 0.f, 0.f, 0.f};
    float accQ[4] = {0.f, 0.f, 0.f, 0.f};

    #pragma unroll 8
    for (int dk = 0; dk < DD; dk += 8) {
        float a0f = aP[dk];
        float a1f = aP[8 * PITCH + dk];
        float a2f = aP[dk + 4];
        float a3f = aP[8 * PITCH + dk + 4];

        uint32_t ah[4], al[4];
        ah[0] = f2tf32(a0f); al[0] = f2tf32(a0f - __uint_as_float(ah[0]));
        ah[1] = f2tf32(a1f); al[1] = f2tf32(a1f - __uint_as_float(ah[1]));
        ah[2] = f2tf32(a2f); al[2] = f2tf32(a2f - __uint_as_float(ah[2]));
        ah[3] = f2tf32(a3f); al[3] = f2tf32(a3f - __uint_as_float(ah[3]));

        uint32_t b0h = __float_as_uint(bH[dk]);
        uint32_t b1h = __float_as_uint(bH[dk + 4]);
        uint32_t b0l = __float_as_uint(bL[dk]);
        uint32_t b1l = __float_as_uint(bL[dk + 4]);

        mma_tf32(accP, ah, b0h, b1h);   // hi*hi
        mma_tf32(accQ, ah, b0l, b1l);   // hi*lo
        mma_tf32(accQ, al, b0h, b1h);   // lo*hi
    }

    // ---- epilogue: 4 outputs per thread ----
    // c0:(g, 2c) c1:(g, 2c+1) c2:(g+8, 2c) c3:(g+8, 2c+1)
    const int rows[2] = { mw + g, mw + g + 8 };
    const int cols[2] = { nw + 2 * c, nw + 2 * c + 1 };

    #pragma unroll
    for (int i = 0; i < 2; i++) {          // row index
        float y2 = s_y2[rows[i]];
        #pragma unroll
        for (int j = 0; j < 2; j++) {      // col index
            int kl = cols[j];
            float gv = accP[i * 2 + j] + accQ[i * 2 + j];
            float s   = s_s[kl];
            float t   = s_t[kl];
            float x2  = s_x2[kl];
            float xa  = s_xa[kl];
            float an2 = s_an2[kl];
            float T   = 1.0f - x2;
            float xy = s * gv;
            float ya = t * gv;
            float S   = fmaf(2.0f, xy, 1.0f) + y2;
            float den = fmaf(2.0f, xy, 1.0f) + x2 * y2;
            float P   = S * S * x2 + 2.0f * S * T * xy + T * T * y2;
            float v   = 2.0f * (S * xa + T * ya) * den / (den * den - P);
            Out[(size_t)(b0 + rows[i]) * KK + (k0 + kl)] = an2 * asinhf(v);
        }
    }
}

extern "C" void kernel_launch(void* const* d_in, const int* in_sizes, int n_in,
                              void* d_out, int out_size)
{
    const float* Y = (const float*)d_in[0];   // output_before (2048, 256)
    const float* Z = (const float*)d_in[1];   // z_mlr (128, 256)
    const float* R = (const float*)d_in[2];   // mlr_r (128, 1)
    float* Out = (float*)d_out;               // (2048, 128)

    size_t shmem = (size_t)(BM * PITCH + 2 * BN * PITCH + NTHREADS + 64 +
                            5 * BN + BM) * sizeof(float);
    cudaFuncSetAttribute(mlr_logits_kernel,
                         cudaFuncAttributeMaxDynamicSharedMemorySize, (int)shmem);

    dim3 grid(BB / BM, KK / BN);   // 32 x 8 = 256 blocks
    dim3 block(NTHREADS);
    mlr_logits_kernel<<<grid, block, shmem>>>(Y, Z, R, Out);
}